// round 15
// baseline (speedup 1.0000x reference)
#include <cuda_runtime.h>
#include <cuda_bf16.h>
#include <cstdint>

#define NPIX   32768      // 8*64*64 pixels
#define DDIM   512
#define NKEYS  2000
#define MKEYS  2048       // padded key count

// ---------------- scratch (static device arrays; allocation-free) ----------
__device__ __align__(256) signed char g_q8[(size_t)NPIX * DDIM];     // 16 MB quantized q
__device__ __align__(256) float       g_qf[(size_t)NPIX * DDIM];     // 64 MB normalized q, fp32
__device__ __align__(256) signed char g_k8[(size_t)MKEYS * DDIM];    // 1 MB quantized keys
__device__ __align__(256) float g_kq[MKEYS];                         // |k|^2 exact (pad = 3e38)
__device__ __align__(256) float g_krk[MKEYS];                        // key dequant: kmax/127
__device__ __align__(256) float g_qrq[NPIX];                         // pixel: 2*qmax*rn/127
__device__ __align__(256) int   g_cand[(size_t)NPIX * 16];           // 16 candidates / pixel

// ---------------- helpers ----------------
__device__ __forceinline__ void mma_s8(int* d, const uint32_t* a, uint32_t b0, uint32_t b1) {
    asm volatile(
        "mma.sync.aligned.m16n8k32.row.col.s32.s8.s8.s32 "
        "{%0,%1,%2,%3}, {%4,%5,%6,%7}, {%8,%9}, {%0,%1,%2,%3};\n"
        : "+r"(d[0]), "+r"(d[1]), "+r"(d[2]), "+r"(d[3])
        : "r"(a[0]), "r"(a[1]), "r"(a[2]), "r"(a[3]), "r"(b0), "r"(b1));
}

// sorted ascending top-2 insert (s[0] best)
__device__ __forceinline__ void ins2(float sc, int idx, float s[2], int id[2]) {
    if (sc < s[1]) {
        if (sc < s[0]) { s[1] = s[0]; id[1] = id[0]; s[0] = sc; id[0] = idx; }
        else           { s[1] = sc;  id[1] = idx; }
    }
}

__device__ __forceinline__ uint32_t pack4(int v0, int v1, int v2, int v3) {
    return (uint32_t)(v0 & 255) | ((uint32_t)(v1 & 255) << 8) |
           ((uint32_t)(v2 & 255) << 16) | ((uint32_t)(v3 & 255) << 24);
}

// =================== kernel 1: key prep (quantize + |k|^2) ===============
__global__ void prep_keys_k(const float* __restrict__ keys) {
    int j = blockIdx.x;          // 0..MKEYS-1
    int t = threadIdx.x;         // 128 threads; 4 dims each
    float4 v = make_float4(0.f, 0.f, 0.f, 0.f);
    float s = 0.f, m = 0.f;
    if (j < NKEYS) {
        v = ((const float4*)(keys + (size_t)j * DDIM))[t];
        s = v.x*v.x + v.y*v.y + v.z*v.z + v.w*v.w;
        m = fmaxf(fmaxf(fabsf(v.x), fabsf(v.y)), fmaxf(fabsf(v.z), fabsf(v.w)));
    }
    #pragma unroll
    for (int o = 16; o; o >>= 1) {
        s += __shfl_xor_sync(0xffffffffu, s, o);
        m = fmaxf(m, __shfl_xor_sync(0xffffffffu, m, o));
    }
    __shared__ float ws[4], wmx[4];
    if ((t & 31) == 0) { ws[t >> 5] = s; wmx[t >> 5] = m; }
    __syncthreads();
    float bs = ws[0] + ws[1] + ws[2] + ws[3];
    float bm = fmaxf(fmaxf(wmx[0], wmx[1]), fmaxf(wmx[2], wmx[3]));
    bm = fmaxf(bm, 1e-20f);
    float qs = 127.f / bm;
    ((uint32_t*)(g_k8 + (size_t)j * DDIM))[t] =
        pack4(__float2int_rn(v.x * qs), __float2int_rn(v.y * qs),
              __float2int_rn(v.z * qs), __float2int_rn(v.w * qs));
    if (t == 0) {
        g_kq[j]  = (j < NKEYS) ? bs : 3.0e38f;
        g_krk[j] = bm / 127.f;
    }
}

// =================== kernel 2: normalize -> int8 + fp32 ===================
__global__ void __launch_bounds__(256) normalize_k(const float* __restrict__ query) {
    extern __shared__ float tile[];            // [512][68]  raw values
    __shared__ float part[16][16][4];
    __shared__ float partm[16][16][4];
    __shared__ float rnw[64];
    __shared__ float qsw[64];                  // 127/rawmax per pixel

    int bh = blockIdx.x;                       // b*64 + h
    int b = bh >> 6, h = bh & 63;
    const float* base = query + (size_t)b * (512 * 4096) + (size_t)h * 64;
    int t = threadIdx.x;

    float a0 = 0.f, a1 = 0.f, a2 = 0.f, a3 = 0.f;
    float m0 = 0.f, m1 = 0.f, m2 = 0.f, m3 = 0.f;
    #pragma unroll
    for (int i = 0; i < 32; i++) {
        int idx = t + i * 256;
        int c = idx >> 4, w4 = idx & 15;
        float4 v = *(const float4*)(base + (size_t)c * 4096 + w4 * 4);
        *(float4*)(tile + c * 68 + w4 * 4) = v;
        a0 = fmaf(v.x, v.x, a0); a1 = fmaf(v.y, v.y, a1);
        a2 = fmaf(v.z, v.z, a2); a3 = fmaf(v.w, v.w, a3);
        m0 = fmaxf(m0, fabsf(v.x)); m1 = fmaxf(m1, fabsf(v.y));
        m2 = fmaxf(m2, fabsf(v.z)); m3 = fmaxf(m3, fabsf(v.w));
    }
    part [t & 15][t >> 4][0] = a0; part [t & 15][t >> 4][1] = a1;
    part [t & 15][t >> 4][2] = a2; part [t & 15][t >> 4][3] = a3;
    partm[t & 15][t >> 4][0] = m0; partm[t & 15][t >> 4][1] = m1;
    partm[t & 15][t >> 4][2] = m2; partm[t & 15][t >> 4][3] = m3;
    __syncthreads();
    if (t < 64) {
        float s = 0.f, qm = 0.f;
        #pragma unroll
        for (int m = 0; m < 16; m++) {
            s += part[t >> 2][m][t & 3];
            qm = fmaxf(qm, partm[t >> 2][m][t & 3]);
        }
        qm = fmaxf(qm, 1e-20f);
        float rn = 1.f / fmaxf(sqrtf(s), 1e-12f);
        rnw[t] = rn;
        qsw[t] = 127.f / qm;                   // int8 = raw * 127/rawmax  (rn cancels)
        g_qrq[bh * 64 + t] = 2.f * qm * rn / 127.f;   // dequant-x2 factor
    }
    __syncthreads();

    int lane = t & 31, warp = t >> 5;
    #pragma unroll
    for (int it = 0; it < 8; it++) {
        int w = warp * 8 + it;
        float rn = rnw[w], qs = qsw[w];
        float* dstf = g_qf + (size_t)(bh * 64 + w) * DDIM;
        #pragma unroll
        for (int j = 0; j < 8; j++) {          // fp32 normalized (for exact rescore)
            int c = j * 64 + lane * 2;
            *(float2*)(dstf + c) = make_float2(tile[c * 68 + w] * rn,
                                               tile[(c + 1) * 68 + w] * rn);
        }
        uint32_t* d8 = (uint32_t*)(g_q8 + (size_t)(bh * 64 + w) * DDIM);
        #pragma unroll
        for (int j = 0; j < 4; j++) {          // int8 quantized (for IMMA)
            int c0 = j * 128 + lane * 4;
            d8[j * 32 + lane] = pack4(
                __float2int_rn(tile[(c0 + 0) * 68 + w] * qs),
                __float2int_rn(tile[(c0 + 1) * 68 + w] * qs),
                __float2int_rn(tile[(c0 + 2) * 68 + w] * qs),
                __float2int_rn(tile[(c0 + 3) * 68 + w] * qs));
        }
    }
}

// =================== kernel 3: IMMA s8 GEMM + per-thread top-2 ============
// 256 CTAs x 256 thr, 2 CTAs/SM (all CTAs resident in one wave).
// A resident [128 rows][528 B] int8 (66KB); B double-buffered, chunk =
// 128 keys x 64 int8, rows of 80 B (2 x 10KB); kq + rk in smem (16KB).
// m16n8k32.s8: fragment layout mirrors the proven 16816 mapping with 4-byte
// k-groups; D layout identical -> fold/writeout unchanged from R12.
// score = |k|^2 - rq[pix] * rk[key] * dot_i32  (dot exact: |dot| < 2^24).
#define SM_A   0
#define SM_B   67584           // 128*528
#define SM_KQ  88064           // SM_B + 2*128*80
#define SM_RK  96256
#define SMEM_G 104448

__global__ void __launch_bounds__(256, 2) gemm_imma_k() {
    extern __shared__ unsigned char sm[];
    float* kqs = (float*)(sm + SM_KQ);
    float* rks = (float*)(sm + SM_RK);

    int t = threadIdx.x, lane = t & 31, warp = t >> 5;
    int wm = warp >> 1, wn = warp & 1;
    int p0 = blockIdx.x * 128;

    // ---- A fill: g_q8 rows -> 528B-stride rows (33 uint4) ----
    {
        const uint4* src = (const uint4*)g_q8 + (size_t)p0 * 32;
        uint4* dst = (uint4*)sm;
        #pragma unroll
        for (int i = 0; i < 16; i++) {
            int idx = t + i * 256;
            int r = idx >> 5, c = idx & 31;
            dst[r * 33 + c] = src[r * 32 + c];
        }
    }
    // ---- kq + rk fills ----
    #pragma unroll
    for (int i = 0; i < 8; i++) kqs[t + i * 256] = g_kq[t + i * 256];
    #pragma unroll
    for (int i = 0; i < 8; i++) rks[t + i * 256] = g_krk[t + i * 256];

    // ---- per-thread B transfer coordinates (512 uint4 per 8KB chunk) ----
    const uint4* kb4 = (const uint4*)g_k8;
    int br_[2], bc_[2];
    #pragma unroll
    for (int i = 0; i < 2; i++) {
        int idx = t + i * 256;
        br_[i] = idx >> 2;            // key row within 128-chunk
        bc_[i] = idx & 3;             // uint4 col within 4 (64 int8)
    }
    uint4 breg[2];
    #pragma unroll
    for (int i = 0; i < 2; i++)       // prefetch chunk g=0
        breg[i] = kb4[(size_t)br_[i] * 32 + bc_[i]];

    // ---- fragment coordinates (proven 16816-style mapping, 4B k-groups) ----
    int ar   = wm * 32 + (lane >> 2);
    int ac4  = (lane & 3) * 4;        // byte offset of k-group
    int bkey = wn * 64 + (lane >> 2);
    int colbase = wn * 64 + (lane & 3) * 2;

    // ---- per-pixel dequant factors for this thread's 4 row slots ----
    float rqv[4];
    #pragma unroll
    for (int s = 0; s < 4; s++) {
        int row = wm * 32 + (s >> 1) * 16 + (s & 1) * 8 + (lane >> 2);
        rqv[s] = g_qrq[p0 + row];
    }

    // ---- per-thread top-2 state: 4 row-slots ----
    float t2s[4][2]; int t2i[4][2];
    #pragma unroll
    for (int s = 0; s < 4; s++) {
        t2s[s][0] = 1e30f; t2s[s][1] = 1e30f;
        t2i[s][0] = 0;     t2i[s][1] = 0;
    }

    int acc[2][8][4];

    #pragma unroll 1
    for (int g = 0; g < 128; g++) {            // g = tile*8 + kc  (16 tiles x 8 K-chunks)
        int tile = g >> 3, kc = g & 7;
        int buf = g & 1;

        // STS prefetched chunk g (single-barrier safe: other buffer's last
        // reads were iter g-2, separated by barrier at g-1)
        {
            unsigned char* bb = sm + SM_B + buf * 10240;
            #pragma unroll
            for (int i = 0; i < 2; i++)
                *(uint4*)(bb + br_[i] * 80 + bc_[i] * 16) = breg[i];
        }
        if (g + 1 < 128) {                     // LDG chunk g+1 (hidden under MMA)
            int g1 = g + 1;
            int t1 = g1 >> 3, k1 = g1 & 7;
            #pragma unroll
            for (int i = 0; i < 2; i++)
                breg[i] = kb4[(size_t)(t1 * 128 + br_[i]) * 32 + k1 * 4 + bc_[i]];
        }
        __syncthreads();                       // B[g] visible (covers A/kq on g=0)

        if (kc == 0) {
            #pragma unroll
            for (int mt = 0; mt < 2; mt++)
                #pragma unroll
                for (int nt = 0; nt < 8; nt++)
                    #pragma unroll
                    for (int k = 0; k < 4; k++) acc[mt][nt][k] = 0;
        }

        const unsigned char* Bp = sm + SM_B + buf * 10240;
        #pragma unroll
        for (int ks = 0; ks < 2; ks++) {       // two k32 steps per 64-int8 chunk
            uint32_t a[2][4];
            #pragma unroll
            for (int mt = 0; mt < 2; mt++) {
                const unsigned char* ap =
                    sm + SM_A + (ar + mt * 16) * 528 + kc * 64 + ks * 32 + ac4;
                a[mt][0] = *(const uint32_t*)(ap);
                a[mt][1] = *(const uint32_t*)(ap + 8 * 528);
                a[mt][2] = *(const uint32_t*)(ap + 16);
                a[mt][3] = *(const uint32_t*)(ap + 8 * 528 + 16);
            }
            #pragma unroll
            for (int nt = 0; nt < 8; nt++) {
                const unsigned char* bp = Bp + (bkey + nt * 8) * 80 + ks * 32 + ac4;
                uint32_t b0 = *(const uint32_t*)(bp);
                uint32_t b1 = *(const uint32_t*)(bp + 16);
                #pragma unroll
                for (int mt = 0; mt < 2; mt++)
                    mma_s8(acc[mt][nt], a[mt], b0, b1);
            }
        }

        if (kc == 7) {                         // fold tile into per-thread top-2
            int kb = tile * 128 + colbase;
            #pragma unroll
            for (int mt = 0; mt < 2; mt++)
                #pragma unroll
                for (int nt = 0; nt < 8; nt++) {
                    int key = kb + nt * 8;
                    float k0 = kqs[key], k1 = kqs[key + 1];
                    float r0 = rks[key], r1 = rks[key + 1];
                    ins2(k0 - rqv[mt*2]   * r0 * (float)acc[mt][nt][0], key,
                         t2s[mt*2],   t2i[mt*2]);
                    ins2(k1 - rqv[mt*2]   * r1 * (float)acc[mt][nt][1], key + 1,
                         t2s[mt*2],   t2i[mt*2]);
                    ins2(k0 - rqv[mt*2+1] * r0 * (float)acc[mt][nt][2], key,
                         t2s[mt*2+1], t2i[mt*2+1]);
                    ins2(k1 - rqv[mt*2+1] * r1 * (float)acc[mt][nt][3], key + 1,
                         t2s[mt*2+1], t2i[mt*2+1]);
                }
        }
    }

    // ---- writeout: every thread writes ITS OWN candidate slots ----
    #pragma unroll
    for (int s = 0; s < 4; s++) {
        int row  = wm * 32 + (s >> 1) * 16 + (s & 1) * 8 + (lane >> 2);
        int slot = (wn * 4 + (lane & 3)) * 2;
        *(int2*)(g_cand + (size_t)(p0 + row) * 16 + slot) =
            make_int2(t2i[s][0], t2i[s][1]);
    }
}

// =================== kernel 4: exact fp32 rescore (16 cands) + L4 =========
__global__ void __launch_bounds__(256) finalize16_k(const float* __restrict__ keys,
                                                    float* __restrict__ out) {
    int warp = threadIdx.x >> 5, lane = threadIdx.x & 31;
    int p = blockIdx.x * 8 + warp;
    const float* q = g_qf + (size_t)p * DDIM;
    float qr[16];
    #pragma unroll
    for (int j = 0; j < 16; j++) qr[j] = q[j * 32 + lane];

    float best = 3.4e38f; int bidx = 0x7fffffff;
    #pragma unroll 1
    for (int c = 0; c < 16; c++) {
        int k = g_cand[(size_t)p * 16 + c];
        const float* kr = keys + (size_t)k * DDIM;
        float d = 0.f;
        #pragma unroll
        for (int j = 0; j < 16; j++) d = fmaf(qr[j], kr[j * 32 + lane], d);
        #pragma unroll
        for (int o = 16; o; o >>= 1) d += __shfl_xor_sync(0xffffffffu, d, o);
        float sc = g_kq[k] - 2.f * d;
        if (sc < best || (sc == best && k < bidx)) { best = sc; bidx = k; }
    }
    const float* kr = keys + (size_t)bidx * DDIM;
    float hs = 0.f;
    #pragma unroll
    for (int j = 0; j < 16; j++) {
        float diff = qr[j] - kr[j * 32 + lane];
        float d2 = diff * diff;
        hs = fmaf(d2, d2, hs);
    }
    #pragma unroll
    for (int o = 16; o; o >>= 1) hs += __shfl_xor_sync(0xffffffffu, hs, o);
    if (lane == 0) out[p] = hs;
}

// =================== launch ===================
extern "C" void kernel_launch(void* const* d_in, const int* in_sizes, int n_in,
                              void* d_out, int out_size) {
    const float* query = (const float*)d_in[0];
    const float* keys  = (const float*)d_in[1];
    if (n_in >= 2 && in_sizes[0] == NKEYS * DDIM) {   // defensive input-order swap
        query = (const float*)d_in[1];
        keys  = (const float*)d_in[0];
    }
    float* out = (float*)d_out;

    cudaFuncSetAttribute(normalize_k, cudaFuncAttributeMaxDynamicSharedMemorySize, 512 * 68 * 4);
    cudaFuncSetAttribute(gemm_imma_k, cudaFuncAttributeMaxDynamicSharedMemorySize, SMEM_G);

    prep_keys_k<<<MKEYS, 128>>>(keys);
    normalize_k<<<512, 256, 512 * 68 * 4>>>(query);
    gemm_imma_k<<<256, 256, SMEM_G>>>();
    finalize16_k<<<NPIX / 8, 256>>>(keys, out);
}

// round 16
// speedup vs baseline: 2.0273x; 2.0273x over previous
#include <cuda_runtime.h>
#include <cuda_bf16.h>
#include <cstdint>

#define NPIX   32768      // 8*64*64 pixels
#define DDIM   512
#define NKEYS  2000
#define MKEYS  2048       // padded key count

// ---------------- scratch (static device arrays; allocation-free) ----------
__device__ __align__(256) __nv_bfloat16 g_qb[(size_t)NPIX * DDIM];   // 32 MB normalized q, bf16
__device__ __align__(256) float         g_qf[(size_t)NPIX * DDIM];   // 64 MB normalized q, fp32
__device__ __align__(256) __nv_bfloat16 g_kb[(size_t)MKEYS * DDIM];  // 2 MB keys, bf16
__device__ __align__(256) float g_kq[MKEYS];                         // |k|^2 (pad = 3e38)
__device__ __align__(256) int   g_cand[(size_t)NPIX * 16];           // 16 candidates / pixel

// ---------------- helpers ----------------
__device__ __forceinline__ void mma_bf16(float* d, const uint32_t* a, uint32_t b0, uint32_t b1) {
    asm volatile(
        "mma.sync.aligned.m16n8k16.row.col.f32.bf16.bf16.f32 "
        "{%0,%1,%2,%3}, {%4,%5,%6,%7}, {%8,%9}, {%0,%1,%2,%3};\n"
        : "+f"(d[0]), "+f"(d[1]), "+f"(d[2]), "+f"(d[3])
        : "r"(a[0]), "r"(a[1]), "r"(a[2]), "r"(a[3]), "r"(b0), "r"(b1));
}

// =================== kernel 1: key prep ===================
__global__ void prep_keys_k(const float* __restrict__ keys) {
    int j = blockIdx.x;          // 0..MKEYS-1
    int t = threadIdx.x;         // 128 threads
    float s = 0.f;
    if (j < NKEYS) {
        float4 v = ((const float4*)(keys + (size_t)j * DDIM))[t];
        s = v.x*v.x + v.y*v.y + v.z*v.z + v.w*v.w;
        __nv_bfloat162* dst = (__nv_bfloat162*)(g_kb + (size_t)j * DDIM);
        dst[2*t+0] = __floats2bfloat162_rn(v.x, v.y);
        dst[2*t+1] = __floats2bfloat162_rn(v.z, v.w);
    } else {
        // exactly ONE row (float2 = 4 bf16; 128 thr x 4 = 512 halves)
        ((float2*)(g_kb + (size_t)j * DDIM))[t] = make_float2(0.f, 0.f);
    }
    #pragma unroll
    for (int o = 16; o; o >>= 1) s += __shfl_xor_sync(0xffffffffu, s, o);
    __shared__ float ws[4];
    if ((t & 31) == 0) ws[t >> 5] = s;
    __syncthreads();
    if (t == 0) g_kq[j] = (j < NKEYS) ? (ws[0] + ws[1] + ws[2] + ws[3]) : 3.0e38f;
}

// =================== kernel 2: normalize + transpose (bf16 + fp32 out) =====
__global__ void __launch_bounds__(256) normalize_k(const float* __restrict__ query) {
    extern __shared__ float tile[];            // [512][68]
    __shared__ float part[16][16][4];
    __shared__ float rnw[64];

    int bh = blockIdx.x;                       // b*64 + h
    int b = bh >> 6, h = bh & 63;
    const float* base = query + (size_t)b * (512 * 4096) + (size_t)h * 64;
    int t = threadIdx.x;

    float a0 = 0.f, a1 = 0.f, a2 = 0.f, a3 = 0.f;
    #pragma unroll
    for (int i = 0; i < 32; i++) {
        int idx = t + i * 256;
        int c = idx >> 4, w4 = idx & 15;
        float4 v = *(const float4*)(base + (size_t)c * 4096 + w4 * 4);
        *(float4*)(tile + c * 68 + w4 * 4) = v;
        a0 = fmaf(v.x, v.x, a0); a1 = fmaf(v.y, v.y, a1);
        a2 = fmaf(v.z, v.z, a2); a3 = fmaf(v.w, v.w, a3);
    }
    part[t & 15][t >> 4][0] = a0; part[t & 15][t >> 4][1] = a1;
    part[t & 15][t >> 4][2] = a2; part[t & 15][t >> 4][3] = a3;
    __syncthreads();
    if (t < 64) {
        float s = 0.f;
        #pragma unroll
        for (int m = 0; m < 16; m++) s += part[t >> 2][m][t & 3];
        rnw[t] = 1.f / fmaxf(sqrtf(s), 1e-12f);
    }
    __syncthreads();

    int lane = t & 31, warp = t >> 5;
    #pragma unroll
    for (int it = 0; it < 8; it++) {
        int w = warp * 8 + it;
        float rn = rnw[w];
        __nv_bfloat162* dstb = (__nv_bfloat162*)(g_qb + (size_t)(bh * 64 + w) * DDIM);
        float* dstf = g_qf + (size_t)(bh * 64 + w) * DDIM;
        #pragma unroll
        for (int j = 0; j < 8; j++) {
            int c = j * 64 + lane * 2;
            float x = tile[c * 68 + w] * rn;
            float y = tile[(c + 1) * 68 + w] * rn;
            dstb[j * 32 + lane] = __floats2bfloat162_rn(x, y);
            *(float2*)(dstf + c) = make_float2(x, y);
        }
    }
}

// =================== kernel 3: HMMA GEMM, 16 warps + per-thread top-1 =====
// 256 CTAs x 512 thr (16 warps, 4x4 warp grid; warp tile 32M x 64N).
// Same A layout / fragment mapping / pipeline as R12 (passing, 333us); the
// change is concurrency: 16 warps (4/SMSP, 2x latency hiding) and B tiles of
// 256 keys (64 loop iterations -> half the barriers). smem 215KB (1 CTA/SM).
// Candidates: per-pixel key space is split over 16 owner threads (4 wn-warps
// x 4 lane-cols); each keeps top-1 of its 128-key subset -> the bf16 argmin
// is ALWAYS some owner's top-1. finalize16 (16 slots) unchanged.
#define SM_A   0
#define SM_B   133120          // 128*520*2
#define SM_KQ  (133120 + 73728)
#define SMEM_G (SM_KQ + 8192)

__global__ void __launch_bounds__(512, 1) gemm_hmma_k() {
    extern __shared__ unsigned char sm[];
    __nv_bfloat16* As = (__nv_bfloat16*)sm;
    float* kqs = (float*)(sm + SM_KQ);

    int t = threadIdx.x, lane = t & 31, warp = t >> 5;
    int wm = warp >> 2, wn = warp & 3;         // 4x4 warp grid
    int p0 = blockIdx.x * 128;

    // ---- A fill: g_qb[p0..p0+127][0..511] -> rows of 520 halves (65 uint4) ----
    {
        const uint4* src = (const uint4*)(g_qb + (size_t)p0 * DDIM);
        uint4* dst = (uint4*)sm;
        #pragma unroll
        for (int i = 0; i < 16; i++) {
            int idx = t + i * 512;
            int r = idx >> 6, c = idx & 63;
            dst[r * 65 + c] = src[r * 64 + c];
        }
    }
    // ---- kq fill ----
    #pragma unroll
    for (int i = 0; i < 4; i++) kqs[t + i * 512] = g_kq[t + i * 512];

    // ---- per-thread B transfer coordinates (2048 uint4 per 32KB chunk) ----
    const uint4* kb4 = (const uint4*)g_kb;
    int br_[4], bc_[4];
    #pragma unroll
    for (int i = 0; i < 4; i++) {
        int idx = t + i * 512;
        br_[i] = idx >> 3;            // key row within 256-chunk
        bc_[i] = idx & 7;             // uint4 col within 8 (64 halves)
    }
    uint4 breg[4];
    #pragma unroll
    for (int i = 0; i < 4; i++)       // prefetch chunk g=0 (tile 0, kc 0)
        breg[i] = kb4[(size_t)br_[i] * 64 + bc_[i]];

    // ---- R12-proven per-lane fragment coordinates ----
    int ar = wm * 32 + (lane >> 2);
    int ac = (lane & 3) * 2;
    int br = wn * 64 + (lane >> 2);
    int bc = (lane & 3) * 2;
    int colbase = wn * 64 + (lane & 3) * 2;

    // ---- per-thread top-1 state: 4 row-slots ----
    float t1s[4]; int t1i[4];
    #pragma unroll
    for (int s = 0; s < 4; s++) { t1s[s] = 1e30f; t1i[s] = 0; }

    float acc[2][8][4];

    #pragma unroll 1
    for (int g = 0; g < 64; g++) {             // g = tile*8 + kc (8 tiles x 8 kc)
        int tile = g >> 3, kc = g & 7;
        int buf = g & 1;

        // STS prefetched chunk g (single-barrier safe: other buffer's last
        // reads were iter g-2, separated by barrier at g-1)
        {
            unsigned char* bb = sm + SM_B + buf * 36864;
            #pragma unroll
            for (int i = 0; i < 4; i++)
                *(uint4*)(bb + br_[i] * 144 + bc_[i] * 16) = breg[i];
        }
        if (g + 1 < 64) {                      // LDG chunk g+1 (hidden under MMA)
            int g1 = g + 1;
            int t1_ = g1 >> 3, k1 = g1 & 7;
            #pragma unroll
            for (int i = 0; i < 4; i++)
                breg[i] = kb4[(size_t)(t1_ * 256 + br_[i]) * 64 + k1 * 8 + bc_[i]];
        }
        __syncthreads();                       // B[g] visible (covers A/kq on g=0)

        if (kc == 0) {
            #pragma unroll
            for (int mt = 0; mt < 2; mt++)
                #pragma unroll
                for (int nt = 0; nt < 8; nt++)
                    #pragma unroll
                    for (int k = 0; k < 4; k++) acc[mt][nt][k] = 0.f;
        }

        const __nv_bfloat16* Bs = (const __nv_bfloat16*)(sm + SM_B + buf * 36864);
        #pragma unroll
        for (int ks = 0; ks < 4; ks++) {
            uint32_t a[2][4];
            #pragma unroll
            for (int mt = 0; mt < 2; mt++) {
                int base = (ar + mt * 16) * 520 + kc * 64 + ks * 16 + ac;
                a[mt][0] = *(const uint32_t*)(As + base);
                a[mt][1] = *(const uint32_t*)(As + base + 8 * 520);
                a[mt][2] = *(const uint32_t*)(As + base + 8);
                a[mt][3] = *(const uint32_t*)(As + base + 8 * 520 + 8);
            }
            #pragma unroll
            for (int nt = 0; nt < 8; nt++) {
                int bb = (br + nt * 8) * 72 + ks * 16 + bc;
                uint32_t b0 = *(const uint32_t*)(Bs + bb);
                uint32_t b1 = *(const uint32_t*)(Bs + bb + 8);
                #pragma unroll
                for (int mt = 0; mt < 2; mt++)
                    mma_bf16(acc[mt][nt], a[mt], b0, b1);
            }
        }

        if (kc == 7) {                         // fold tile into per-thread top-1
            int kb = tile * 256 + colbase;
            #pragma unroll
            for (int mt = 0; mt < 2; mt++)
                #pragma unroll
                for (int nt = 0; nt < 8; nt++) {
                    int key = kb + nt * 8;
                    float s0 = kqs[key]     - 2.f * acc[mt][nt][0];
                    float s1 = kqs[key + 1] - 2.f * acc[mt][nt][1];
                    float s2 = kqs[key]     - 2.f * acc[mt][nt][2];
                    float s3 = kqs[key + 1] - 2.f * acc[mt][nt][3];
                    if (s0 < t1s[mt*2])   { t1s[mt*2]   = s0; t1i[mt*2]   = key;     }
                    if (s1 < t1s[mt*2])   { t1s[mt*2]   = s1; t1i[mt*2]   = key + 1; }
                    if (s2 < t1s[mt*2+1]) { t1s[mt*2+1] = s2; t1i[mt*2+1] = key;     }
                    if (s3 < t1s[mt*2+1]) { t1s[mt*2+1] = s3; t1i[mt*2+1] = key + 1; }
                }
        }
    }

    // ---- writeout: every thread writes ITS OWN candidate slot ----
    // pixel row = wm*32 + (s>>1)*16 + (s&1)*8 + (lane>>2); slot = wn*4+(lane&3)
    #pragma unroll
    for (int s = 0; s < 4; s++) {
        int row  = wm * 32 + (s >> 1) * 16 + (s & 1) * 8 + (lane >> 2);
        int slot = wn * 4 + (lane & 3);
        g_cand[(size_t)(p0 + row) * 16 + slot] = t1i[s];
    }
}

// =================== kernel 4: exact fp32 rescore (16 cands) + L4 =========
__global__ void __launch_bounds__(256) finalize16_k(const float* __restrict__ keys,
                                                    float* __restrict__ out) {
    int warp = threadIdx.x >> 5, lane = threadIdx.x & 31;
    int p = blockIdx.x * 8 + warp;
    const float* q = g_qf + (size_t)p * DDIM;
    float qr[16];
    #pragma unroll
    for (int j = 0; j < 16; j++) qr[j] = q[j * 32 + lane];

    float best = 3.4e38f; int bidx = 0x7fffffff;
    #pragma unroll 1
    for (int c = 0; c < 16; c++) {
        int k = g_cand[(size_t)p * 16 + c];
        const float* kr = keys + (size_t)k * DDIM;
        float d = 0.f;
        #pragma unroll
        for (int j = 0; j < 16; j++) d = fmaf(qr[j], kr[j * 32 + lane], d);
        #pragma unroll
        for (int o = 16; o; o >>= 1) d += __shfl_xor_sync(0xffffffffu, d, o);
        float sc = g_kq[k] - 2.f * d;
        if (sc < best || (sc == best && k < bidx)) { best = sc; bidx = k; }
    }
    const float* kr = keys + (size_t)bidx * DDIM;
    float hs = 0.f;
    #pragma unroll
    for (int j = 0; j < 16; j++) {
        float diff = qr[j] - kr[j * 32 + lane];
        float d2 = diff * diff;
        hs = fmaf(d2, d2, hs);
    }
    #pragma unroll
    for (int o = 16; o; o >>= 1) hs += __shfl_xor_sync(0xffffffffu, hs, o);
    if (lane == 0) out[p] = hs;
}

// =================== launch ===================
extern "C" void kernel_launch(void* const* d_in, const int* in_sizes, int n_in,
                              void* d_out, int out_size) {
    const float* query = (const float*)d_in[0];
    const float* keys  = (const float*)d_in[1];
    if (n_in >= 2 && in_sizes[0] == NKEYS * DDIM) {   // defensive input-order swap
        query = (const float*)d_in[1];
        keys  = (const float*)d_in[0];
    }
    float* out = (float*)d_out;

    cudaFuncSetAttribute(normalize_k, cudaFuncAttributeMaxDynamicSharedMemorySize, 512 * 68 * 4);
    cudaFuncSetAttribute(gemm_hmma_k, cudaFuncAttributeMaxDynamicSharedMemorySize, SMEM_G);

    prep_keys_k<<<MKEYS, 128>>>(keys);
    normalize_k<<<512, 256, 512 * 68 * 4>>>(query);
    gemm_hmma_k<<<256, 512, SMEM_G>>>();
    finalize16_k<<<NPIX / 8, 256>>>(keys, out);
}